// round 2
// baseline (speedup 1.0000x reference)
#include <cuda_runtime.h>
#include <math.h>

#define N_NODESK 50000
#define N_EDGESK 800000
#define F_INK    128
#define C1K      256     // HEADS*HID
#define HEADSK   8

// ---------------- scratch (device globals: allocation-free contract) ----------------
__device__ float g_h1[N_NODESK * C1K];     // x @ W1            (51.2 MB)
__device__ float g_hout[N_NODESK * C1K];   // elu(layer1 out)   (51.2 MB)
__device__ float g_as1[N_NODESK * HEADSK];
__device__ float g_ad1[N_NODESK * HEADSK];
__device__ float g_h2[N_NODESK * 2];
__device__ float g_as2[N_NODESK];
__device__ float g_ad2[N_NODESK];
__device__ int   g_cnt[N_NODESK];
__device__ int   g_rowptr[N_NODESK + 1];
__device__ int   g_cursor[N_NODESK];
__device__ int   g_col[N_EDGESK];          // src ids grouped by dst

// ---------------- CSR build ----------------
__global__ void zero_cnt_kernel() {
    int i = blockIdx.x * blockDim.x + threadIdx.x;
    if (i < N_NODESK) g_cnt[i] = 0;
}

__global__ void hist_kernel(const int* __restrict__ dst) {
    int e = blockIdx.x * blockDim.x + threadIdx.x;
    if (e < N_EDGESK) atomicAdd(&g_cnt[dst[e]], 1);
}

// single-block inclusive-scan -> exclusive row_ptr (+ cursor copy)
__global__ void scan_kernel() {
    __shared__ int sh[1024];
    __shared__ int carry;
    if (threadIdx.x == 0) carry = 0;
    __syncthreads();
    for (int base = 0; base < N_NODESK; base += 1024) {
        int i = base + threadIdx.x;
        int v = (i < N_NODESK) ? g_cnt[i] : 0;
        sh[threadIdx.x] = v;
        __syncthreads();
        for (int off = 1; off < 1024; off <<= 1) {
            int t = (threadIdx.x >= off) ? sh[threadIdx.x - off] : 0;
            __syncthreads();
            sh[threadIdx.x] += t;
            __syncthreads();
        }
        int excl = sh[threadIdx.x] - v;
        if (i < N_NODESK) {
            g_rowptr[i] = carry + excl;
            g_cursor[i] = carry + excl;
        }
        __syncthreads();
        if (threadIdx.x == 1023) carry += sh[1023];
        __syncthreads();
    }
    if (threadIdx.x == 0) g_rowptr[N_NODESK] = carry;
}

__global__ void scatter_kernel(const int* __restrict__ src, const int* __restrict__ dst) {
    int e = blockIdx.x * blockDim.x + threadIdx.x;
    if (e < N_EDGESK) {
        int pos = atomicAdd(&g_cursor[dst[e]], 1);
        g_col[pos] = src[e];
    }
}

// ---------------- SGEMM: g_h1 = x[M,128] @ W1[128,256] ----------------
__global__ __launch_bounds__(256) void sgemm_kernel(const float* __restrict__ A,
                                                    const float* __restrict__ B) {
    const int K = F_INK, N = C1K;
    __shared__ float As[16][64];
    __shared__ float Bs[16][64];
    int tid = threadIdx.x;
    int tx = tid & 15, ty = tid >> 4;
    int bm = blockIdx.y * 64, bn = blockIdx.x * 64;
    int arow = tid >> 2, acg = tid & 3;
    int brow = tid >> 4, bcg = tid & 15;
    int grow = bm + arow;
    float acc[4][4];
#pragma unroll
    for (int i = 0; i < 4; i++)
#pragma unroll
        for (int j = 0; j < 4; j++) acc[i][j] = 0.f;

    for (int kt = 0; kt < K; kt += 16) {
        float4 av = make_float4(0.f, 0.f, 0.f, 0.f);
        if (grow < N_NODESK)
            av = *(const float4*)(A + (size_t)grow * K + kt + acg * 4);
        As[acg * 4 + 0][arow] = av.x;
        As[acg * 4 + 1][arow] = av.y;
        As[acg * 4 + 2][arow] = av.z;
        As[acg * 4 + 3][arow] = av.w;
        *(float4*)&Bs[brow][bcg * 4] =
            *(const float4*)(B + (size_t)(kt + brow) * N + bn + bcg * 4);
        __syncthreads();
#pragma unroll
        for (int k = 0; k < 16; k++) {
            float4 a = *(const float4*)&As[k][ty * 4];
            float4 b = *(const float4*)&Bs[k][tx * 4];
            acc[0][0] += a.x * b.x; acc[0][1] += a.x * b.y; acc[0][2] += a.x * b.z; acc[0][3] += a.x * b.w;
            acc[1][0] += a.y * b.x; acc[1][1] += a.y * b.y; acc[1][2] += a.y * b.z; acc[1][3] += a.y * b.w;
            acc[2][0] += a.z * b.x; acc[2][1] += a.z * b.y; acc[2][2] += a.z * b.z; acc[2][3] += a.z * b.w;
            acc[3][0] += a.w * b.x; acc[3][1] += a.w * b.y; acc[3][2] += a.w * b.z; acc[3][3] += a.w * b.w;
        }
        __syncthreads();
    }
#pragma unroll
    for (int i = 0; i < 4; i++) {
        int r = bm + ty * 4 + i;
        if (r < N_NODESK) {
            float4 o = make_float4(acc[i][0], acc[i][1], acc[i][2], acc[i][3]);
            *(float4*)(g_h1 + (size_t)r * N + bn + tx * 4) = o;
        }
    }
}

// ---------------- alpha1: per (node, head) dot of h1 slice with a1 vectors ----------------
__global__ void alpha1_kernel(const float* __restrict__ a_src, const float* __restrict__ a_dst) {
    int t = blockIdx.x * blockDim.x + threadIdx.x;
    if (t >= N_NODESK * HEADSK) return;
    int n = t >> 3, h = t & 7;
    const float4* hr = (const float4*)(g_h1 + (size_t)n * C1K + h * 32);
    const float4* av = (const float4*)(a_src + h * 32);
    const float4* bv = (const float4*)(a_dst + h * 32);
    float s = 0.f, d = 0.f;
#pragma unroll
    for (int i = 0; i < 8; i++) {
        float4 v = hr[i];
        float4 a = av[i];
        float4 b = bv[i];
        s += v.x * a.x + v.y * a.y + v.z * a.z + v.w * a.w;
        d += v.x * b.x + v.y * b.y + v.z * b.z + v.w * b.w;
    }
    g_as1[t] = s;
    g_ad1[t] = d;
}

__device__ __forceinline__ float lrelu02(float x) { return x > 0.f ? x : 0.2f * x; }
__device__ __forceinline__ float eluf(float x)    { return x > 0.f ? x : expm1f(x); }

// ---------------- layer-1 aggregation: warp per dst node (CSR gather) ----------------
// lane l owns channels [4l,4l+3] (head l/8) and [128+4l,128+4l+3] (head 4+l/8).
// out = elu( (Σ_e w_e * h1[src_e]) / (Σ_e w_e) + b1 ), softmax done without max-shift.
__global__ __launch_bounds__(256) void agg1_kernel(const float* __restrict__ b1) {
    int warp = (blockIdx.x * blockDim.x + threadIdx.x) >> 5;
    int lane = threadIdx.x & 31;
    if (warp >= N_NODESK) return;
    int n = warp;
    int hA = lane >> 3, hB = 4 + (lane >> 3);
    float adA = g_ad1[n * 8 + hA];
    float adB = g_ad1[n * 8 + hB];
    float4 accA = make_float4(0.f, 0.f, 0.f, 0.f);
    float4 accB = make_float4(0.f, 0.f, 0.f, 0.f);
    float denA = 0.f, denB = 0.f;
    int beg = g_rowptr[n], end = g_rowptr[n + 1];
    for (int e = beg - 1; e < end; ++e) {       // e == beg-1 is the self loop
        int s = (e < beg) ? n : g_col[e];
        float wA = expf(lrelu02(g_as1[s * 8 + hA] + adA));
        float wB = expf(lrelu02(g_as1[s * 8 + hB] + adB));
        const float4* row = (const float4*)(g_h1 + (size_t)s * C1K);
        float4 vA = row[lane];
        float4 vB = row[32 + lane];
        accA.x += wA * vA.x; accA.y += wA * vA.y; accA.z += wA * vA.z; accA.w += wA * vA.w;
        accB.x += wB * vB.x; accB.y += wB * vB.y; accB.z += wB * vB.z; accB.w += wB * vB.w;
        denA += wA; denB += wB;
    }
    float rA = 1.f / denA, rB = 1.f / denB;
    const float4 bA = *(const float4*)(b1 + 4 * lane);
    const float4 bB = *(const float4*)(b1 + 128 + 4 * lane);
    float4 oA, oB;
    oA.x = eluf(accA.x * rA + bA.x); oA.y = eluf(accA.y * rA + bA.y);
    oA.z = eluf(accA.z * rA + bA.z); oA.w = eluf(accA.w * rA + bA.w);
    oB.x = eluf(accB.x * rB + bB.x); oB.y = eluf(accB.y * rB + bB.y);
    oB.z = eluf(accB.z * rB + bB.z); oB.w = eluf(accB.w * rB + bB.w);
    float4* orow = (float4*)(g_hout + (size_t)n * C1K);
    orow[lane] = oA;
    orow[32 + lane] = oB;
}

// ---------------- layer-2 node kernel: h2 = hout @ W2, plus alpha2_src/dst ----------------
__global__ __launch_bounds__(256) void l2node_kernel(const float* __restrict__ W2,
                                                     const float* __restrict__ a2s,
                                                     const float* __restrict__ a2d) {
    int warp = (blockIdx.x * blockDim.x + threadIdx.x) >> 5;
    int lane = threadIdx.x & 31;
    if (warp >= N_NODESK) return;
    const float4* row = (const float4*)(g_hout + (size_t)warp * C1K);
    float4 vA = row[lane];
    float4 vB = row[32 + lane];
    int cA = 4 * lane, cB = 128 + 4 * lane;
    float acc0 = 0.f, acc1 = 0.f;
    acc0 += vA.x * W2[(cA + 0) * 2] + vA.y * W2[(cA + 1) * 2] + vA.z * W2[(cA + 2) * 2] + vA.w * W2[(cA + 3) * 2];
    acc1 += vA.x * W2[(cA + 0) * 2 + 1] + vA.y * W2[(cA + 1) * 2 + 1] + vA.z * W2[(cA + 2) * 2 + 1] + vA.w * W2[(cA + 3) * 2 + 1];
    acc0 += vB.x * W2[(cB + 0) * 2] + vB.y * W2[(cB + 1) * 2] + vB.z * W2[(cB + 2) * 2] + vB.w * W2[(cB + 3) * 2];
    acc1 += vB.x * W2[(cB + 0) * 2 + 1] + vB.y * W2[(cB + 1) * 2 + 1] + vB.z * W2[(cB + 2) * 2 + 1] + vB.w * W2[(cB + 3) * 2 + 1];
#pragma unroll
    for (int o = 16; o; o >>= 1) {
        acc0 += __shfl_xor_sync(0xffffffffu, acc0, o);
        acc1 += __shfl_xor_sync(0xffffffffu, acc1, o);
    }
    if (lane == 0) {
        g_h2[warp * 2 + 0] = acc0;
        g_h2[warp * 2 + 1] = acc1;
        g_as2[warp] = acc0 * a2s[0] + acc1 * a2s[1];
        g_ad2[warp] = acc0 * a2d[0] + acc1 * a2d[1];
    }
}

// ---------------- layer-2 aggregation: thread per dst node -> d_out ----------------
__global__ void agg2_kernel(const float* __restrict__ b2, float* __restrict__ out) {
    int n = blockIdx.x * blockDim.x + threadIdx.x;
    if (n >= N_NODESK) return;
    float adn = g_ad2[n];
    int beg = g_rowptr[n], end = g_rowptr[n + 1];
    float den = 0.f, o0 = 0.f, o1 = 0.f;
    for (int e = beg - 1; e < end; ++e) {
        int s = (e < beg) ? n : g_col[e];
        float w = expf(lrelu02(g_as2[s] + adn));
        den += w;
        o0 += w * g_h2[s * 2 + 0];
        o1 += w * g_h2[s * 2 + 1];
    }
    float r = 1.f / den;
    out[n * 2 + 0] = o0 * r + b2[0];
    out[n * 2 + 1] = o1 * r + b2[1];
}

// ---------------- launch ----------------
extern "C" void kernel_launch(void* const* d_in, const int* in_sizes, int n_in,
                              void* d_out, int out_size) {
    const float* x    = (const float*)d_in[0];
    const int*   ei   = (const int*)d_in[1];
    const float* W1   = (const float*)d_in[3];
    const float* a1s  = (const float*)d_in[4];
    const float* a1d  = (const float*)d_in[5];
    const float* b1   = (const float*)d_in[6];
    const float* W2   = (const float*)d_in[7];
    const float* a2s  = (const float*)d_in[8];
    const float* a2d  = (const float*)d_in[9];
    const float* b2   = (const float*)d_in[10];
    float* out = (float*)d_out;

    const int* src = ei;
    const int* dst = ei + N_EDGESK;

    // CSR build
    zero_cnt_kernel<<<(N_NODESK + 255) / 256, 256>>>();
    hist_kernel<<<(N_EDGESK + 255) / 256, 256>>>(dst);
    scan_kernel<<<1, 1024>>>();
    scatter_kernel<<<(N_EDGESK + 255) / 256, 256>>>(src, dst);

    // layer 1
    sgemm_kernel<<<dim3(C1K / 64, (N_NODESK + 63) / 64), 256>>>(x, W1);
    alpha1_kernel<<<(N_NODESK * HEADSK + 255) / 256, 256>>>(a1s, a1d);
    agg1_kernel<<<(N_NODESK * 32 + 255) / 256, 256>>>(b1);

    // layer 2
    l2node_kernel<<<(N_NODESK * 32 + 255) / 256, 256>>>(W2, a2s, a2d);
    agg2_kernel<<<(N_NODESK + 255) / 256, 256>>>(b2, out);
}